// round 2
// baseline (speedup 1.0000x reference)
#include <cuda_runtime.h>
#include <math.h>

// ---------------------------------------------------------------------------
// QuantumDenseNet: CV quantum circuit simulator. C=6, N=5, state=6^5=7776 c64.
// R2: packed fp32x2 FMA (Blackwell dual-rate fp32) + 2col x 18row register
// blocking in the beamsplitter apply. Gates stored pre-splatted as float4
// (ux, uy, -uy, ux) so each complex madd = 2x fma.rn.f32x2.
// ---------------------------------------------------------------------------

typedef unsigned long long ull;

__device__ float4 g_bs[80][1296];  // BS gates, row-major [out36][in36], splat-packed
__device__ float4 g_sm[40][36];    // per layer: 5 squeeze then 5 disp, 6x6, packed

__device__ __forceinline__ void cmadd(float2& a, float2 u, float2 v) {
    a.x = fmaf(u.x, v.x, fmaf(-u.y, v.y, a.x));
    a.y = fmaf(u.x, v.y, fmaf(u.y, v.x, a.y));
}
__device__ __forceinline__ float2 cmul(float2 u, float2 v) {
    return make_float2(u.x * v.x - u.y * v.y, u.x * v.y + u.y * v.x);
}

__device__ __forceinline__ ull pack2(float lo, float hi) {
    ull r;
    asm("mov.b64 %0, {%1, %2};" : "=l"(r) : "f"(lo), "f"(hi));
    return r;
}
__device__ __forceinline__ float2 unpack2(ull v) {
    float lo, hi;
    asm("mov.b64 {%0, %1}, %2;" : "=f"(lo), "=f"(hi) : "l"(v));
    return make_float2(lo, hi);
}
__device__ __forceinline__ void fma2(ull& d, ull a, ull b) {
    asm("fma.rn.f32x2 %0, %1, %2, %0;" : "+l"(d) : "l"(a), "l"(b));
}

// ---------------------------------------------------------------------------
// Precompute: beamsplitter gates (order-16 Horner Taylor + 6 squarings,
// matching the reference _expm). Output splat-packed.
// ---------------------------------------------------------------------------
__global__ void prep_bs_kernel(const float* __restrict__ lin) {
    __shared__ float2 sH[1296], sA[1296], sB[1296];
    int gid = blockIdx.x;                  // 0..79
    int l = gid / 20, rem = gid % 20, h = rem / 10, n = rem % 10;
    const float* p = lin + l * 63;
    float theta = h ? p[29 + n] : p[n];
    float phi   = h ? p[39 + n] : p[10 + n];
    float sp, cp;
    sincosf(phi, &sp, &cp);
    int tid = threadIdx.x;

    for (int e = tid; e < 1296; e += blockDim.x) {
        int row = e / 36, col = e % 36;
        int a = row / 6, bq = row % 6, c = col / 6, d = col % 6;
        float2 v = make_float2(0.f, 0.f);
        if (c == a + 1 && d == bq - 1) {         // ep * kron(A, AD)
            float m = theta * sqrtf((float)((a + 1) * bq));
            v.x += m * cp; v.y += m * sp;
        }
        if (c == a - 1 && d == bq + 1) {         // -conj(ep) * kron(AD, A)
            float m = theta * sqrtf((float)(a * (bq + 1)));
            v.x -= m * cp; v.y += m * sp;
        }
        sH[e] = make_float2(v.x * (1.f / 64.f), v.y * (1.f / 64.f));
        sA[e] = make_float2(row == col ? 1.f : 0.f, 0.f);
    }
    __syncthreads();

    float2* pa = sA;
    float2* pb = sB;
    for (int k = 16; k >= 1; k--) {
        float inv = 1.f / (float)k;
        for (int e = tid; e < 1296; e += blockDim.x) {
            int row = e / 36, col = e % 36;
            float2 acc = make_float2(0.f, 0.f);
            for (int j = 0; j < 36; j++) cmadd(acc, sH[row * 36 + j], pa[j * 36 + col]);
            pb[e] = make_float2((row == col ? 1.f : 0.f) + acc.x * inv, acc.y * inv);
        }
        __syncthreads();
        float2* t = pa; pa = pb; pb = t;
    }
    for (int s = 0; s < 6; s++) {
        for (int e = tid; e < 1296; e += blockDim.x) {
            int row = e / 36, col = e % 36;
            float2 acc = make_float2(0.f, 0.f);
            for (int j = 0; j < 36; j++) cmadd(acc, pa[row * 36 + j], pa[j * 36 + col]);
            pb[e] = acc;
        }
        __syncthreads();
        float2* t = pa; pa = pb; pb = t;
    }
    for (int e = tid; e < 1296; e += blockDim.x) {
        float2 u = pa[e];
        g_bs[gid][e] = make_float4(u.x, u.y, -u.y, u.x);
    }
}

// ---------------------------------------------------------------------------
// Precompute: squeeze (r10<5) / displacement (r10>=5) 6x6 gates, packed.
// ---------------------------------------------------------------------------
__global__ void prep_sm_kernel(const float* __restrict__ lin) {
    __shared__ float2 sH[36], sA[36], sB[36];
    int gid = blockIdx.x;                 // 0..39
    int l = gid / 10, r10 = gid % 10;
    int isdisp = (r10 >= 5);
    int i = r10 % 5;
    const float* p = lin + l * 63;
    int e = threadIdx.x;                  // blockDim = 36
    int row = e / 6, col = e % 6;

    float2 hv = make_float2(0.f, 0.f);
    if (!isdisp) {
        float rr = p[24 + i];
        if (col == row + 2) hv.x = rr * 0.5f * sqrtf((float)((row + 1) * (row + 2)));
        if (row == col + 2) hv.x = -rr * 0.5f * sqrtf((float)((col + 1) * (col + 2)));
    } else {
        float dr = p[53 + i], dphi = p[58 + i];
        float s, c;
        sincosf(dphi, &s, &c);
        if (row == col + 1) { float m = dr * sqrtf((float)row); hv.x = m * c;  hv.y = m * s; }
        if (col == row + 1) { float m = dr * sqrtf((float)col); hv.x = -m * c; hv.y = m * s; }
    }
    sH[e] = make_float2(hv.x * (1.f / 64.f), hv.y * (1.f / 64.f));
    sA[e] = make_float2(row == col ? 1.f : 0.f, 0.f);
    __syncthreads();

    float2* pa = sA;
    float2* pb = sB;
    for (int k = 16; k >= 1; k--) {
        float inv = 1.f / (float)k;
        float2 acc = make_float2(0.f, 0.f);
        #pragma unroll
        for (int j = 0; j < 6; j++) cmadd(acc, sH[row * 6 + j], pa[j * 6 + col]);
        pb[e] = make_float2((row == col ? 1.f : 0.f) + acc.x * inv, acc.y * inv);
        __syncthreads();
        float2* t = pa; pa = pb; pb = t;
    }
    for (int s = 0; s < 6; s++) {
        float2 acc = make_float2(0.f, 0.f);
        #pragma unroll
        for (int j = 0; j < 6; j++) cmadd(acc, pa[row * 6 + j], pa[j * 6 + col]);
        pb[e] = acc;
        __syncthreads();
        float2* t = pa; pa = pb; pb = t;
    }
    float2 u = pa[e];
    g_sm[gid][e] = make_float4(u.x, u.y, -u.y, u.x);
}

// ---------------------------------------------------------------------------
// Main kernel helpers (state + scratch in dynamic smem)
// ---------------------------------------------------------------------------

// Single-mode 6x6 gate, fiber-per-thread (in-place safe), packed FMA2.
__device__ __forceinline__ void apply_sm(float2* psi, float4* sU4, int tid,
                                         const float4* __restrict__ Ug, int m) {
    if (tid < 36) sU4[tid] = Ug[tid];
    __syncthreads();
    int s = (m == 0) ? 1296 : (m == 1) ? 216 : (m == 2) ? 36 : (m == 3) ? 6 : 1;
    for (int f = tid; f < 1296; f += 256) {
        int hi = f / s, lo = f - hi * s;
        int base = hi * (s * 6) + lo;
        ull vx[6], vy[6];
        #pragma unroll
        for (int t = 0; t < 6; t++) {
            float2 v = psi[base + t * s];
            vx[t] = pack2(v.x, v.x);
            vy[t] = pack2(v.y, v.y);
        }
        #pragma unroll
        for (int r = 0; r < 6; r++) {
            ull acc = 0ull;
            #pragma unroll
            for (int t = 0; t < 6; t++) {
                ulonglong2 u = *reinterpret_cast<const ulonglong2*>(&sU4[r * 6 + t]);
                fma2(acc, u.x, vx[t]);
                fma2(acc, u.y, vy[t]);
            }
            psi[base + r * s] = unpack2(acc);
        }
    }
    __syncthreads();
}

// Beamsplitter 36x36 gate on modes (m, m+1). 216 fibers; each thread handles
// 2 columns x 18 rows (2-col blocking halves gate LDS traffic). Row splitting
// means two threads share a fiber -> barrier between read and write phases.
__device__ __forceinline__ void apply_bs(float2* psi, float4* sU4, int tid,
                                         const float4* __restrict__ Ug, int m) {
    for (int i = tid; i < 1296; i += 256) sU4[i] = Ug[i];
    __syncthreads();
    int s = (m == 0) ? 216 : (m == 1) ? 36 : (m == 2) ? 6 : 1;

    bool active = tid < 216;
    int h  = (tid >= 108) ? 1 : 0;            // row half
    int cp = h ? tid - 108 : tid;             // column pair 0..107
    int f0 = cp * 2, f1 = f0 + 1;
    int hi0 = f0 / s, lo0 = f0 - hi0 * s;
    int hi1 = f1 / s, lo1 = f1 - hi1 * s;
    int base0 = hi0 * (s * 36) + lo0;
    int base1 = hi1 * (s * 36) + lo1;
    int r0 = h * 18;

    ull acc0[18], acc1[18];
    if (active) {
        #pragma unroll
        for (int r = 0; r < 18; r++) { acc0[r] = 0ull; acc1[r] = 0ull; }
        for (int j = 0; j < 36; j++) {
            float2 v0 = psi[base0 + j * s];
            float2 v1 = psi[base1 + j * s];
            ull v0x = pack2(v0.x, v0.x), v0y = pack2(v0.y, v0.y);
            ull v1x = pack2(v1.x, v1.x), v1y = pack2(v1.y, v1.y);
            const float4* up = sU4 + r0 * 36 + j;
            #pragma unroll
            for (int r = 0; r < 18; r++) {
                ulonglong2 u = *reinterpret_cast<const ulonglong2*>(up + r * 36);
                fma2(acc0[r], u.x, v0x);
                fma2(acc0[r], u.y, v0y);
                fma2(acc1[r], u.x, v1x);
                fma2(acc1[r], u.y, v1y);
            }
        }
    }
    __syncthreads();   // all reads of psi complete before any writes
    if (active) {
        #pragma unroll
        for (int r = 0; r < 18; r++) {
            psi[base0 + (r0 + r) * s] = unpack2(acc0[r]);
            psi[base1 + (r0 + r) * s] = unpack2(acc1[r]);
        }
    }
    __syncthreads();
}

// Fused diagonal gate: rot (phase p*n) or kerr (p*n^2), nmodes modes.
__device__ __forceinline__ void apply_diag(float2* psi, float2* sD, int tid,
                                           const float* __restrict__ params,
                                           int nmodes, bool kerr) {
    if (tid < 30) {
        int mm = tid / 6, n = tid % 6;
        float ph = 0.f;
        if (mm < nmodes) {
            float pv = params[mm];
            ph = kerr ? pv * (float)(n * n) : pv * (float)n;
        }
        float s, c;
        sincosf(ph, &s, &c);
        sD[tid] = make_float2(c, s);
    }
    __syncthreads();
    for (int idx = tid; idx < 7776; idx += 256) {
        int t2 = idx;
        int n4 = t2 % 6; t2 /= 6;
        int n3 = t2 % 6; t2 /= 6;
        int n2 = t2 % 6; t2 /= 6;
        int n1 = t2 % 6;
        int n0 = t2 / 6;
        float2 f = cmul(sD[n0], sD[6 + n1]);
        f = cmul(f, sD[12 + n2]);
        f = cmul(f, sD[18 + n3]);
        f = cmul(f, sD[24 + n4]);
        psi[idx] = cmul(psi[idx], f);
    }
    __syncthreads();
}

// ---------------------------------------------------------------------------
// Main kernel: one CTA per batch element.
// Dynamic smem: psi[7776] float2 (62208B) + sU4[1296] float4 (20736B) = 82944B
// ---------------------------------------------------------------------------
__global__ __launch_bounds__(256, 2)
void qnet_kernel(const float* __restrict__ x, const float* __restrict__ lin,
                 const float* __restrict__ act, const float* __restrict__ lact,
                 float* __restrict__ out) {
    extern __shared__ float2 smem[];
    float2* psi = smem;                        // 7776 float2
    float4* sU4 = (float4*)(smem + 7776);      // 1296 float4 (gate stage/scratch)
    float2* sD  = (float2*)sU4;                // diag table view
    float*  sS  = (float*)sU4;                 // raw float scratch view
    const int tid = threadIdx.x;
    const int b = blockIdx.x;

    // ---- initial displacement vectors: v_i = col0 of expm(x_i*(AD - A)) ----
    {
        float* sG  = sS;           // 180 floats
        float* sR0 = sS + 180;     // 180
        float* sR1 = sS + 360;     // 180
        float* sV  = sS + 540;     // 30
        int g = tid / 36, e = tid % 36;
        bool on = (tid < 180);
        int row = e / 6, col = e % 6;
        if (on) {
            float xv = x[b * 5 + g];
            float gv = 0.f;
            if (row == col + 1) gv += sqrtf((float)row);   // AD
            if (col == row + 1) gv -= sqrtf((float)col);   // -A
            sG[g * 36 + e] = xv * gv * (1.f / 64.f);
            sR0[g * 36 + e] = (row == col) ? 1.f : 0.f;
        }
        __syncthreads();
        float* pa = sR0;
        float* pb = sR1;
        for (int k = 16; k >= 1; k--) {
            if (on) {
                float acc = 0.f;
                #pragma unroll
                for (int j = 0; j < 6; j++) acc += sG[g * 36 + row * 6 + j] * pa[g * 36 + j * 6 + col];
                pb[g * 36 + e] = ((row == col) ? 1.f : 0.f) + acc * (1.f / (float)k);
            }
            __syncthreads();
            float* t = pa; pa = pb; pb = t;
        }
        for (int s = 0; s < 6; s++) {
            if (on) {
                float acc = 0.f;
                #pragma unroll
                for (int j = 0; j < 6; j++) acc += pa[g * 36 + row * 6 + j] * pa[g * 36 + j * 6 + col];
                pb[g * 36 + e] = acc;
            }
            __syncthreads();
            float* t = pa; pa = pb; pb = t;
        }
        if (on && col == 0) sV[g * 6 + row] = pa[g * 36 + row * 6];
        __syncthreads();

        for (int idx = tid; idx < 7776; idx += 256) {
            int t2 = idx;
            int n4 = t2 % 6; t2 /= 6;
            int n3 = t2 % 6; t2 /= 6;
            int n2 = t2 % 6; t2 /= 6;
            int n1 = t2 % 6;
            int n0 = t2 / 6;
            float v = sV[n0] * sV[6 + n1] * sV[12 + n2] * sV[18 + n3] * sV[24 + n4];
            psi[idx] = make_float2(v, 0.f);
        }
        __syncthreads();
    }

    // ---- circuit ----
    const int km[10] = {0, 2, 1, 3, 0, 2, 1, 3, 0, 2};
    for (int l = 0; l < 4; l++) {
        const float* p = lin + l * 63;
        for (int n = 0; n < 10; n++) apply_bs(psi, sU4, tid, g_bs[l * 20 + n], km[n]);
        apply_diag(psi, sD, tid, p + 20, 4, false);                              // rot 1
        for (int i = 0; i < 5; i++) apply_sm(psi, sU4, tid, g_sm[l * 10 + i], i);        // squeeze
        for (int n = 0; n < 10; n++) apply_bs(psi, sU4, tid, g_bs[l * 20 + 10 + n], km[n]);
        apply_diag(psi, sD, tid, p + 49, 4, false);                              // rot 2
        for (int i = 0; i < 5; i++) apply_sm(psi, sU4, tid, g_sm[l * 10 + 5 + i], i);    // disp
        if (l < 3) apply_diag(psi, sD, tid, act + l * 5, 5, true);               // kerr
    }
    apply_diag(psi, sD, tid, lact, 2, true);                                     // final kerr

    // ---- expectation <psi|(A+AD)_i|psi> ----
    float s0 = 0.f, s1 = 0.f;
    for (int idx = tid; idx < 7776; idx += 256) {
        float2 a = psi[idx];
        int n0 = idx / 1296;
        int n1 = (idx / 216) % 6;
        if (n0 < 5) {
            float2 bb = psi[idx + 1296];
            s0 += sqrtf((float)(n0 + 1)) * (a.x * bb.x + a.y * bb.y);
        }
        if (n1 < 5) {
            float2 bb = psi[idx + 216];
            s1 += sqrtf((float)(n1 + 1)) * (a.x * bb.x + a.y * bb.y);
        }
    }
    #pragma unroll
    for (int off = 16; off; off >>= 1) {
        s0 += __shfl_down_sync(0xffffffffu, s0, off);
        s1 += __shfl_down_sync(0xffffffffu, s1, off);
    }
    __syncthreads();
    float* sRed = sS;
    if ((tid & 31) == 0) {
        sRed[(tid >> 5) * 2] = s0;
        sRed[(tid >> 5) * 2 + 1] = s1;
    }
    __syncthreads();
    if (tid == 0) {
        float t0 = 0.f, t1 = 0.f;
        for (int w = 0; w < 8; w++) { t0 += sRed[2 * w]; t1 += sRed[2 * w + 1]; }
        out[b * 2 + 0] = 2.f * t0;
        out[b * 2 + 1] = 2.f * t1;
    }
}

// ---------------------------------------------------------------------------
extern "C" void kernel_launch(void* const* d_in, const int* in_sizes, int n_in,
                              void* d_out, int out_size) {
    const float* x    = (const float*)d_in[0];   // (B,5)
    const float* lin  = (const float*)d_in[1];   // (4,63)
    const float* act  = (const float*)d_in[2];   // (3,5)
    const float* lact = (const float*)d_in[3];   // (5,)
    float* out = (float*)d_out;                  // (B,2)
    int B = in_sizes[0] / 5;

    cudaFuncSetAttribute(qnet_kernel, cudaFuncAttributeMaxDynamicSharedMemorySize, 82944);

    prep_bs_kernel<<<80, 256>>>(lin);
    prep_sm_kernel<<<40, 36>>>(lin);
    qnet_kernel<<<B, 256, 82944>>>(x, lin, act, lact, out);
}

// round 4
// speedup vs baseline: 2.1346x; 2.1346x over previous
#include <cuda_runtime.h>
#include <math.h>

// ---------------------------------------------------------------------------
// QuantumDenseNet: CV quantum circuit simulator. C=6, N=5, state=6^5=7776 c64.
// R3 (resubmit; prior round was an infra failure, not a kernel result):
// R1 structure (one fiber per thread, known-good 10.4ms) with ONLY the inner
// math changed to packed fp32x2 FMA: gates stored as (ux,uy,-uy,ux), each
// complex madd = 1x LDS.128 + 2x fma.rn.f32x2 (was 1x LDS.64 + 4x FFMA).
// ---------------------------------------------------------------------------

typedef unsigned long long ull;

__device__ float4 g_bs[80][1296];  // BS gates, row-major [out36][in36], splat-packed
__device__ float4 g_sm[40][36];    // per layer: 5 squeeze then 5 disp, 6x6, packed

__device__ __forceinline__ void cmadd(float2& a, float2 u, float2 v) {
    a.x = fmaf(u.x, v.x, fmaf(-u.y, v.y, a.x));
    a.y = fmaf(u.x, v.y, fmaf(u.y, v.x, a.y));
}
__device__ __forceinline__ float2 cmul(float2 u, float2 v) {
    return make_float2(u.x * v.x - u.y * v.y, u.x * v.y + u.y * v.x);
}

__device__ __forceinline__ ull pack2(float lo, float hi) {
    ull r;
    asm("mov.b64 %0, {%1, %2};" : "=l"(r) : "f"(lo), "f"(hi));
    return r;
}
__device__ __forceinline__ float2 unpack2(ull v) {
    float lo, hi;
    asm("mov.b64 {%0, %1}, %2;" : "=f"(lo), "=f"(hi) : "l"(v));
    return make_float2(lo, hi);
}
__device__ __forceinline__ void fma2(ull& d, ull a, ull b) {
    asm("fma.rn.f32x2 %0, %1, %2, %0;" : "+l"(d) : "l"(a), "l"(b));
}

// ---------------------------------------------------------------------------
// Precompute: beamsplitter gates (order-16 Horner Taylor + 6 squarings,
// matching the reference _expm). Output splat-packed.
// ---------------------------------------------------------------------------
__global__ void prep_bs_kernel(const float* __restrict__ lin) {
    __shared__ float2 sH[1296], sA[1296], sB[1296];
    int gid = blockIdx.x;                  // 0..79
    int l = gid / 20, rem = gid % 20, h = rem / 10, n = rem % 10;
    const float* p = lin + l * 63;
    float theta = h ? p[29 + n] : p[n];
    float phi   = h ? p[39 + n] : p[10 + n];
    float sp, cp;
    sincosf(phi, &sp, &cp);
    int tid = threadIdx.x;

    for (int e = tid; e < 1296; e += blockDim.x) {
        int row = e / 36, col = e % 36;
        int a = row / 6, bq = row % 6, c = col / 6, d = col % 6;
        float2 v = make_float2(0.f, 0.f);
        if (c == a + 1 && d == bq - 1) {         // ep * kron(A, AD)
            float m = theta * sqrtf((float)((a + 1) * bq));
            v.x += m * cp; v.y += m * sp;
        }
        if (c == a - 1 && d == bq + 1) {         // -conj(ep) * kron(AD, A)
            float m = theta * sqrtf((float)(a * (bq + 1)));
            v.x -= m * cp; v.y += m * sp;
        }
        sH[e] = make_float2(v.x * (1.f / 64.f), v.y * (1.f / 64.f));
        sA[e] = make_float2(row == col ? 1.f : 0.f, 0.f);
    }
    __syncthreads();

    float2* pa = sA;
    float2* pb = sB;
    for (int k = 16; k >= 1; k--) {
        float inv = 1.f / (float)k;
        for (int e = tid; e < 1296; e += blockDim.x) {
            int row = e / 36, col = e % 36;
            float2 acc = make_float2(0.f, 0.f);
            for (int j = 0; j < 36; j++) cmadd(acc, sH[row * 36 + j], pa[j * 36 + col]);
            pb[e] = make_float2((row == col ? 1.f : 0.f) + acc.x * inv, acc.y * inv);
        }
        __syncthreads();
        float2* t = pa; pa = pb; pb = t;
    }
    for (int s = 0; s < 6; s++) {
        for (int e = tid; e < 1296; e += blockDim.x) {
            int row = e / 36, col = e % 36;
            float2 acc = make_float2(0.f, 0.f);
            for (int j = 0; j < 36; j++) cmadd(acc, pa[row * 36 + j], pa[j * 36 + col]);
            pb[e] = acc;
        }
        __syncthreads();
        float2* t = pa; pa = pb; pb = t;
    }
    for (int e = tid; e < 1296; e += blockDim.x) {
        float2 u = pa[e];
        g_bs[gid][e] = make_float4(u.x, u.y, -u.y, u.x);
    }
}

// ---------------------------------------------------------------------------
// Precompute: squeeze (r10<5) / displacement (r10>=5) 6x6 gates, packed.
// ---------------------------------------------------------------------------
__global__ void prep_sm_kernel(const float* __restrict__ lin) {
    __shared__ float2 sH[36], sA[36], sB[36];
    int gid = blockIdx.x;                 // 0..39
    int l = gid / 10, r10 = gid % 10;
    int isdisp = (r10 >= 5);
    int i = r10 % 5;
    const float* p = lin + l * 63;
    int e = threadIdx.x;                  // blockDim = 36
    int row = e / 6, col = e % 6;

    float2 hv = make_float2(0.f, 0.f);
    if (!isdisp) {
        float rr = p[24 + i];
        if (col == row + 2) hv.x = rr * 0.5f * sqrtf((float)((row + 1) * (row + 2)));
        if (row == col + 2) hv.x = -rr * 0.5f * sqrtf((float)((col + 1) * (col + 2)));
    } else {
        float dr = p[53 + i], dphi = p[58 + i];
        float s, c;
        sincosf(dphi, &s, &c);
        if (row == col + 1) { float m = dr * sqrtf((float)row); hv.x = m * c;  hv.y = m * s; }
        if (col == row + 1) { float m = dr * sqrtf((float)col); hv.x = -m * c; hv.y = m * s; }
    }
    sH[e] = make_float2(hv.x * (1.f / 64.f), hv.y * (1.f / 64.f));
    sA[e] = make_float2(row == col ? 1.f : 0.f, 0.f);
    __syncthreads();

    float2* pa = sA;
    float2* pb = sB;
    for (int k = 16; k >= 1; k--) {
        float inv = 1.f / (float)k;
        float2 acc = make_float2(0.f, 0.f);
        #pragma unroll
        for (int j = 0; j < 6; j++) cmadd(acc, sH[row * 6 + j], pa[j * 6 + col]);
        pb[e] = make_float2((row == col ? 1.f : 0.f) + acc.x * inv, acc.y * inv);
        __syncthreads();
        float2* t = pa; pa = pb; pb = t;
    }
    for (int s = 0; s < 6; s++) {
        float2 acc = make_float2(0.f, 0.f);
        #pragma unroll
        for (int j = 0; j < 6; j++) cmadd(acc, pa[row * 6 + j], pa[j * 6 + col]);
        pb[e] = acc;
        __syncthreads();
        float2* t = pa; pa = pb; pb = t;
    }
    float2 u = pa[e];
    g_sm[gid][e] = make_float4(u.x, u.y, -u.y, u.x);
}

// ---------------------------------------------------------------------------
// Main kernel helpers (state + scratch in dynamic smem)
// ---------------------------------------------------------------------------

// Single-mode 6x6 gate, fiber-per-thread (in-place safe), packed FMA2.
__device__ __forceinline__ void apply_sm(float2* psi, float4* sU4, int tid,
                                         const float4* __restrict__ Ug, int m) {
    if (tid < 36) sU4[tid] = Ug[tid];
    __syncthreads();
    int s = (m == 0) ? 1296 : (m == 1) ? 216 : (m == 2) ? 36 : (m == 3) ? 6 : 1;
    for (int f = tid; f < 1296; f += 256) {
        int hi = f / s, lo = f - hi * s;
        int base = hi * (s * 6) + lo;
        ull vx[6], vy[6];
        #pragma unroll
        for (int t = 0; t < 6; t++) {
            float2 v = psi[base + t * s];
            vx[t] = pack2(v.x, v.x);
            vy[t] = pack2(v.y, v.y);
        }
        #pragma unroll
        for (int r = 0; r < 6; r++) {
            ull acc = 0ull;
            #pragma unroll
            for (int t = 0; t < 6; t++) {
                ulonglong2 u = *reinterpret_cast<const ulonglong2*>(&sU4[r * 6 + t]);
                fma2(acc, u.x, vx[t]);
                fma2(acc, u.y, vy[t]);
            }
            psi[base + r * s] = unpack2(acc);
        }
    }
    __syncthreads();
}

// Beamsplitter 36x36 gate on modes (m, m+1). Same mapping as R1: 216 fibers,
// one whole fiber per thread, acc[36] in registers -> in-place safe.
// Only the inner math differs from R1: LDS.128 of packed gate + 2x fma2.
__device__ __forceinline__ void apply_bs(float2* psi, float4* sU4, int tid,
                                         const float4* __restrict__ Ug, int m) {
    for (int i = tid; i < 1296; i += 256) sU4[i] = Ug[i];
    __syncthreads();
    int s = (m == 0) ? 216 : (m == 1) ? 36 : (m == 2) ? 6 : 1;
    if (tid < 216) {
        int hi = tid / s, lo = tid - hi * s;
        int base = hi * (s * 36) + lo;
        ull acc[36];
        #pragma unroll
        for (int r = 0; r < 36; r++) acc[r] = 0ull;
        #pragma unroll 4
        for (int j = 0; j < 36; j++) {
            float2 v = psi[base + j * s];
            ull vx = pack2(v.x, v.x);
            ull vy = pack2(v.y, v.y);
            #pragma unroll
            for (int r = 0; r < 36; r++) {
                ulonglong2 u = *reinterpret_cast<const ulonglong2*>(&sU4[r * 36 + j]);
                fma2(acc[r], u.x, vx);
                fma2(acc[r], u.y, vy);
            }
        }
        #pragma unroll
        for (int r = 0; r < 36; r++) psi[base + r * s] = unpack2(acc[r]);
    }
    __syncthreads();
}

// Fused diagonal gate: rot (phase p*n) or kerr (p*n^2), nmodes modes.
__device__ __forceinline__ void apply_diag(float2* psi, float2* sD, int tid,
                                           const float* __restrict__ params,
                                           int nmodes, bool kerr) {
    if (tid < 30) {
        int mm = tid / 6, n = tid % 6;
        float ph = 0.f;
        if (mm < nmodes) {
            float pv = params[mm];
            ph = kerr ? pv * (float)(n * n) : pv * (float)n;
        }
        float s, c;
        sincosf(ph, &s, &c);
        sD[tid] = make_float2(c, s);
    }
    __syncthreads();
    for (int idx = tid; idx < 7776; idx += 256) {
        int t2 = idx;
        int n4 = t2 % 6; t2 /= 6;
        int n3 = t2 % 6; t2 /= 6;
        int n2 = t2 % 6; t2 /= 6;
        int n1 = t2 % 6;
        int n0 = t2 / 6;
        float2 f = cmul(sD[n0], sD[6 + n1]);
        f = cmul(f, sD[12 + n2]);
        f = cmul(f, sD[18 + n3]);
        f = cmul(f, sD[24 + n4]);
        psi[idx] = cmul(psi[idx], f);
    }
    __syncthreads();
}

// ---------------------------------------------------------------------------
// Main kernel: one CTA per batch element.
// Dynamic smem: psi[7776] float2 (62208B) + sU4[1296] float4 (20736B) = 82944B
// ---------------------------------------------------------------------------
__global__ __launch_bounds__(256, 2)
void qnet_kernel(const float* __restrict__ x, const float* __restrict__ lin,
                 const float* __restrict__ act, const float* __restrict__ lact,
                 float* __restrict__ out) {
    extern __shared__ float2 smem[];
    float2* psi = smem;                        // 7776 float2
    float4* sU4 = (float4*)(smem + 7776);      // 1296 float4 (gate stage/scratch)
    float2* sD  = (float2*)sU4;                // diag table view
    float*  sS  = (float*)sU4;                 // raw float scratch view
    const int tid = threadIdx.x;
    const int b = blockIdx.x;

    // ---- initial displacement vectors: v_i = col0 of expm(x_i*(AD - A)) ----
    {
        float* sG  = sS;           // 180 floats
        float* sR0 = sS + 180;     // 180
        float* sR1 = sS + 360;     // 180
        float* sV  = sS + 540;     // 30
        int g = tid / 36, e = tid % 36;
        bool on = (tid < 180);
        int row = e / 6, col = e % 6;
        if (on) {
            float xv = x[b * 5 + g];
            float gv = 0.f;
            if (row == col + 1) gv += sqrtf((float)row);   // AD
            if (col == row + 1) gv -= sqrtf((float)col);   // -A
            sG[g * 36 + e] = xv * gv * (1.f / 64.f);
            sR0[g * 36 + e] = (row == col) ? 1.f : 0.f;
        }
        __syncthreads();
        float* pa = sR0;
        float* pb = sR1;
        for (int k = 16; k >= 1; k--) {
            if (on) {
                float acc = 0.f;
                #pragma unroll
                for (int j = 0; j < 6; j++) acc += sG[g * 36 + row * 6 + j] * pa[g * 36 + j * 6 + col];
                pb[g * 36 + e] = ((row == col) ? 1.f : 0.f) + acc * (1.f / (float)k);
            }
            __syncthreads();
            float* t = pa; pa = pb; pb = t;
        }
        for (int s = 0; s < 6; s++) {
            if (on) {
                float acc = 0.f;
                #pragma unroll
                for (int j = 0; j < 6; j++) acc += pa[g * 36 + row * 6 + j] * pa[g * 36 + j * 6 + col];
                pb[g * 36 + e] = acc;
            }
            __syncthreads();
            float* t = pa; pa = pb; pb = t;
        }
        if (on && col == 0) sV[g * 6 + row] = pa[g * 36 + row * 6];
        __syncthreads();

        for (int idx = tid; idx < 7776; idx += 256) {
            int t2 = idx;
            int n4 = t2 % 6; t2 /= 6;
            int n3 = t2 % 6; t2 /= 6;
            int n2 = t2 % 6; t2 /= 6;
            int n1 = t2 % 6;
            int n0 = t2 / 6;
            float v = sV[n0] * sV[6 + n1] * sV[12 + n2] * sV[18 + n3] * sV[24 + n4];
            psi[idx] = make_float2(v, 0.f);
        }
        __syncthreads();
    }

    // ---- circuit ----
    const int km[10] = {0, 2, 1, 3, 0, 2, 1, 3, 0, 2};
    for (int l = 0; l < 4; l++) {
        const float* p = lin + l * 63;
        for (int n = 0; n < 10; n++) apply_bs(psi, sU4, tid, g_bs[l * 20 + n], km[n]);
        apply_diag(psi, sD, tid, p + 20, 4, false);                              // rot 1
        for (int i = 0; i < 5; i++) apply_sm(psi, sU4, tid, g_sm[l * 10 + i], i);        // squeeze
        for (int n = 0; n < 10; n++) apply_bs(psi, sU4, tid, g_bs[l * 20 + 10 + n], km[n]);
        apply_diag(psi, sD, tid, p + 49, 4, false);                              // rot 2
        for (int i = 0; i < 5; i++) apply_sm(psi, sU4, tid, g_sm[l * 10 + 5 + i], i);    // disp
        if (l < 3) apply_diag(psi, sD, tid, act + l * 5, 5, true);               // kerr
    }
    apply_diag(psi, sD, tid, lact, 2, true);                                     // final kerr

    // ---- expectation <psi|(A+AD)_i|psi> ----
    float s0 = 0.f, s1 = 0.f;
    for (int idx = tid; idx < 7776; idx += 256) {
        float2 a = psi[idx];
        int n0 = idx / 1296;
        int n1 = (idx / 216) % 6;
        if (n0 < 5) {
            float2 bb = psi[idx + 1296];
            s0 += sqrtf((float)(n0 + 1)) * (a.x * bb.x + a.y * bb.y);
        }
        if (n1 < 5) {
            float2 bb = psi[idx + 216];
            s1 += sqrtf((float)(n1 + 1)) * (a.x * bb.x + a.y * bb.y);
        }
    }
    #pragma unroll
    for (int off = 16; off; off >>= 1) {
        s0 += __shfl_down_sync(0xffffffffu, s0, off);
        s1 += __shfl_down_sync(0xffffffffu, s1, off);
    }
    __syncthreads();
    float* sRed = sS;
    if ((tid & 31) == 0) {
        sRed[(tid >> 5) * 2] = s0;
        sRed[(tid >> 5) * 2 + 1] = s1;
    }
    __syncthreads();
    if (tid == 0) {
        float t0 = 0.f, t1 = 0.f;
        for (int w = 0; w < 8; w++) { t0 += sRed[2 * w]; t1 += sRed[2 * w + 1]; }
        out[b * 2 + 0] = 2.f * t0;
        out[b * 2 + 1] = 2.f * t1;
    }
}

// ---------------------------------------------------------------------------
extern "C" void kernel_launch(void* const* d_in, const int* in_sizes, int n_in,
                              void* d_out, int out_size) {
    const float* x    = (const float*)d_in[0];   // (B,5)
    const float* lin  = (const float*)d_in[1];   // (4,63)
    const float* act  = (const float*)d_in[2];   // (3,5)
    const float* lact = (const float*)d_in[3];   // (5,)
    float* out = (float*)d_out;                  // (B,2)
    int B = in_sizes[0] / 5;

    cudaFuncSetAttribute(qnet_kernel, cudaFuncAttributeMaxDynamicSharedMemorySize, 82944);

    prep_bs_kernel<<<80, 256>>>(lin);
    prep_sm_kernel<<<40, 36>>>(lin);
    qnet_kernel<<<B, 256, 82944>>>(x, lin, act, lact, out);
}